// round 6
// baseline (speedup 1.0000x reference)
#include <cuda_runtime.h>
#include <math.h>

// Fixed shapes: x = (64, 256, 4096) fp32 -> out (64, 256, 816)
#define SEQ      4096
#define MIN_W    20
#define STRIDE   5
#define OUT_LEN  816            // (4096-20)/5 + 1
#define GROUPS   204            // 816 / 4 windows per worker thread
#define EPS      1e-8f
#define NTHREADS 256

// Exact XLA GPU warp-shuffle reduction tree for the 20-element window sum
// (lanes 20..31 carry identity 0; shfl-down 16,8,4,2,1). Bitwise-pinned:
// every add is a single rn FADD, no reassociation, no FMA. The MEAN must be
// bitwise-matched to the reference: global L2 rel_err is dominated by
// near-zero-mean windows where cv = std/(mean+eps) ~ 1e7.
__device__ __forceinline__ float xla_tree20(const float* __restrict__ v)
{
    float c0 = __fadd_rn(__fadd_rn(v[0], v[16]), v[8]);
    float c1 = __fadd_rn(__fadd_rn(v[1], v[17]), v[9]);
    float c2 = __fadd_rn(__fadd_rn(v[2], v[18]), v[10]);
    float c3 = __fadd_rn(__fadd_rn(v[3], v[19]), v[11]);
    float c4 = __fadd_rn(v[4], v[12]);
    float c5 = __fadd_rn(v[5], v[13]);
    float c6 = __fadd_rn(v[6], v[14]);
    float c7 = __fadd_rn(v[7], v[15]);
    float d0 = __fadd_rn(c0, c4);
    float d1 = __fadd_rn(c1, c5);
    float d2 = __fadd_rn(c2, c6);
    float d3 = __fadd_rn(c3, c7);
    return __fadd_rn(__fadd_rn(d0, d2), __fadd_rn(d1, d3));
}

__device__ __forceinline__ float sqrt_approx(float a)
{
    float r;
    asm("sqrt.approx.f32 %0, %1;" : "=f"(r) : "f"(a));
    return r;
}

__device__ __forceinline__ void stg_cs_f4(float* p, float4 v)
{
    asm volatile("st.global.cs.v4.f32 [%0], {%1, %2, %3, %4};"
                 :: "l"(p), "f"(v.x), "f"(v.y), "f"(v.z), "f"(v.w)
                 : "memory");
}

// One CTA per (batch, feature) row.
// Phase 1: fully coalesced row load into smem (4 LDG.128 / thread; each warp
//          instruction touches exactly 4 lines -> minimal L1tex wavefronts).
// Phase 2: 204 workers each take 4 consecutive windows; its 36 elements are
//          9 LDS.128 at lane-stride 80B. 80B = 5 x 16B units, 5 odd ->
//          lanes cover all 32 banks exactly once per 8-lane phase:
//          conflict-free vector smem reads.
__global__ __launch_bounds__(NTHREADS) void tscv_kernel(
    const float* __restrict__ x,
    float*       __restrict__ out)
{
    __shared__ float row[SEQ];

    const int r = blockIdx.x;

    // ---- Phase 1: stage row ----
    {
        const float4* __restrict__ src4 =
            reinterpret_cast<const float4*>(x + (size_t)r * SEQ);
        float4* row4 = reinterpret_cast<float4*>(row);
        #pragma unroll
        for (int i = 0; i < SEQ / 4 / NTHREADS; ++i) {
            row4[threadIdx.x + i * NTHREADS] = src4[threadIdx.x + i * NTHREADS];
        }
    }
    __syncthreads();

    // ---- Phase 2: compute ----
    const int loc = threadIdx.x;
    if (loc < GROUPS) {
        // 9 conflict-free LDS.128: elements [20*loc, 20*loc + 36)
        float v[36];
        const float4* row4 =
            reinterpret_cast<const float4*>(row + MIN_W * loc);
        #pragma unroll
        for (int i = 0; i < 9; ++i) {
            const float4 t = row4[i];
            v[4 * i + 0] = t.x;
            v[4 * i + 1] = t.y;
            v[4 * i + 2] = t.z;
            v[4 * i + 3] = t.w;
        }

        // Shared chunk sums of squares: cs[i] = sum v[5i..5i+4]^2.
        float cs[7];
        #pragma unroll
        for (int i = 0; i < 7; ++i) {
            const float* c = v + 5 * i;
            float a = __fmul_rn(c[0], c[0]);
            a = __fmaf_rn(c[1], c[1], a);
            a = __fmaf_rn(c[2], c[2], a);
            a = __fmaf_rn(c[3], c[3], a);
            a = __fmaf_rn(c[4], c[4], a);
            cs[i] = a;
        }

        float res[4];
        #pragma unroll
        for (int j = 0; j < 4; ++j) {
            const float* w = v + STRIDE * j;

            // Exact mean: pinned-order tree sum, then recip-mult.
            const float s    = xla_tree20(w);
            const float mean = __fmul_rn(s, 0.05f);

            // sumsq from shared chunks; sum((x-m)^2) = sumsq - 2ms + 20m^2.
            const float sumsq = __fadd_rn(__fadd_rn(cs[j],     cs[j + 1]),
                                          __fadd_rn(cs[j + 2], cs[j + 3]));
            const float ss  = __fmaf_rn(mean,
                                        __fmaf_rn(20.0f, mean, -2.0f * s),
                                        sumsq);
            const float var = fmaxf(ss, 0.0f) * (float)(1.0 / 19.0);
            const float sd  = sqrt_approx(var);

            float cv = __fdividef(sd, __fadd_rn(mean, EPS));
            res[j] = (cv != cv) ? 0.0f : cv;   // NaN -> 0
        }

        float4 o;
        o.x = res[0]; o.y = res[1]; o.z = res[2]; o.w = res[3];
        stg_cs_f4(out + (size_t)r * OUT_LEN + 4 * loc, o);
    }
}

extern "C" void kernel_launch(void* const* d_in, const int* in_sizes, int n_in,
                              void* d_out, int out_size)
{
    const float* x = (const float*)d_in[0];
    float* out = (float*)d_out;

    const int n_rows = in_sizes[0] / SEQ;   // 16384
    tscv_kernel<<<n_rows, NTHREADS>>>(x, out);
}